// round 3
// baseline (speedup 1.0000x reference)
#include <cuda_runtime.h>

typedef unsigned long long ull;

#define KT       181
#define OPT      16                  // outputs per thread (2 per acc pair, 8 pairs)
#define NTHREADS 128
#define TILE_T   (NTHREADS * OPT)    // 2048 outputs per block
#define SU_LEN   2248                // TILE_T + 196 window floats, padded to /8
#define KPAD     184                 // padded tap count (even)

__device__ __forceinline__ ull pk2(float lo, float hi) {
    ull r; asm("mov.b64 %0, {%1, %2};" : "=l"(r) : "f"(lo), "f"(hi)); return r;
}
__device__ __forceinline__ void upk2(ull v, float& lo, float& hi) {
    asm("mov.b64 {%0, %1}, %2;" : "=f"(lo), "=f"(hi) : "l"(v));
}
__device__ __forceinline__ ull ffma2(ull a, ull b, ull c) {
    ull d; asm("fma.rn.f32x2 %0, %1, %2, %3;" : "=l"(d) : "l"(a), "l"(b), "l"(c)); return d;
}

// FIR via packed f32x2: out[b,t] = sum_i krev[i] * u[b,t+i], krev reversed taps.
// Dual window pairs: P[i]=(w[2i],w[2i+1]) aligned, Q[i]=(w[2i+1],w[2i+2]) odd.
// Even tap 2m -> P[m+p]; odd tap 2m+1 -> Q[m+p]  (p = acc-pair index, 0..7).
__global__ __launch_bounds__(NTHREADS)
void fir_f32x2_kernel(const float* __restrict__ u,
                      const float* __restrict__ kern,
                      float* __restrict__ out,
                      int t_out, int t_in)
{
    __shared__ __align__(16) float s_u[SU_LEN];
    __shared__ __align__(8)  float2 s_k2[KPAD];

    const int row = blockIdx.y;
    const int t0  = blockIdx.x * TILE_T;
    const int tid = threadIdx.x;

    const float* __restrict__ urow = u + (long long)row * t_in;

    // ---- stage duplicated reversed taps ----
    for (int i = tid; i < KPAD; i += NTHREADS) {
        float v = (i < KT) ? kern[KT - 1 - i] : 0.0f;
        s_k2[i] = make_float2(v, v);
    }

    // ---- stage input tile ----
    if (((t_in & 3) == 0) && ((t0 & 3) == 0)) {
        for (int i4 = tid; i4 < SU_LEN / 4; i4 += NTHREADS) {
            int g = t0 + i4 * 4;
            float4 v;
            if (g + 3 < t_in) {
                v = reinterpret_cast<const float4*>(urow + g)[0];
            } else {
                v.x = (g     < t_in) ? urow[g]     : 0.0f;
                v.y = (g + 1 < t_in) ? urow[g + 1] : 0.0f;
                v.z = (g + 2 < t_in) ? urow[g + 2] : 0.0f;
                v.w = (g + 3 < t_in) ? urow[g + 3] : 0.0f;
            }
            reinterpret_cast<float4*>(s_u)[i4] = v;
        }
    } else {
        for (int i = tid; i < SU_LEN; i += NTHREADS) {
            int g = t0 + i;
            s_u[i] = (g < t_in) ? urow[g] : 0.0f;
        }
    }
    __syncthreads();

    const int t_local = tid * OPT;
    const int t       = t0 + t_local;
    if (t >= t_out) return;   // no barriers below

    const float* __restrict__ w = s_u + t_local;   // per-thread window base

    ull acc[8];
    #pragma unroll
    for (int p = 0; p < 8; p++) acc[p] = 0ull;

    ull P[12], Q[12];
    float wlast;

    // ---- init: floats 0..23 -> P[0..11], Q[0..10] ----
    {
        float tmp[24];
        #pragma unroll
        for (int q = 0; q < 6; q++) {
            float4 v = reinterpret_cast<const float4*>(w)[q];
            tmp[4*q+0] = v.x; tmp[4*q+1] = v.y; tmp[4*q+2] = v.z; tmp[4*q+3] = v.w;
        }
        #pragma unroll
        for (int i = 0; i < 12; i++) P[i] = pk2(tmp[2*i], tmp[2*i+1]);
        #pragma unroll
        for (int i = 0; i < 11; i++) Q[i] = pk2(tmp[2*i+1], tmp[2*i+2]);
        Q[11] = 0ull;
        wlast = tmp[23];
    }

    const ull* __restrict__ k2 = reinterpret_cast<const ull*>(s_k2);

    // ---- main loop: 21 chunks of 8 taps (taps 0..167), unrolled by 3 so the
    //      mod-12 ring indices are compile-time constants ----
    #pragma unroll 1
    for (int oc = 0; oc < 7; oc++) {
        const int c0 = oc * 3;
        #pragma unroll
        for (int s = 0; s < 3; s++) {
            const int b  = 4 * s;            // ring phase: 0,4,8 (static)
            const int j0 = (c0 + s) * 8;     // tap base (runtime uniform)
            // 8 taps (4 even/odd pairs)
            #pragma unroll
            for (int m = 0; m < 4; m++) {
                ull ke = k2[j0 + 2*m];
                ull ko = k2[j0 + 2*m + 1];
                #pragma unroll
                for (int p = 0; p < 8; p++) {
                    acc[p] = ffma2(ke, P[(b + m + p) % 12], acc[p]);
                    acc[p] = ffma2(ko, Q[(b + m + p) % 12], acc[p]);
                }
            }
            // advance window by 8 floats: load floats [8c+24, 8c+32)
            {
                const float* nw = w + (c0 + s) * 8 + 24;
                float4 A = reinterpret_cast<const float4*>(nw)[0];
                float4 B = reinterpret_cast<const float4*>(nw)[1];
                P[(b + 0) % 12] = pk2(A.x, A.y);
                P[(b + 1) % 12] = pk2(A.z, A.w);
                P[(b + 2) % 12] = pk2(B.x, B.y);
                P[(b + 3) % 12] = pk2(B.z, B.w);
                Q[(b + 11) % 12] = pk2(wlast, A.x);
                Q[(b + 0)  % 12] = pk2(A.y, A.z);
                Q[(b + 1)  % 12] = pk2(A.w, B.x);
                Q[(b + 2)  % 12] = pk2(B.y, B.z);
                wlast = B.w;
            }
        }
    }

    // ---- tail: taps 168..180 (13 taps). Ring holds P[84..95], Q[84..94],
    //      wlast = float 191. Extend with floats 192..195. ----
    ull px0, px1, qx0, qx1;   // P[96],P[97],Q[95],Q[96]
    {
        float4 C = reinterpret_cast<const float4*>(w + 192)[0];
        px0 = pk2(C.x, C.y);           // floats 192,193
        px1 = pk2(C.z, C.w);           // floats 194,195
        qx0 = pk2(wlast, C.x);         // floats 191,192
        qx1 = pk2(C.y, C.z);           // floats 193,194
    }
    #pragma unroll
    for (int mm = 0; mm < 7; mm++) {          // m = 84+mm, even taps 168..180
        ull ke = k2[168 + 2*mm];
        #pragma unroll
        for (int p = 0; p < 8; p++) {
            const int i = 84 + mm + p;        // 84..97
            ull pv = (i <= 95) ? P[i % 12] : ((i == 96) ? px0 : px1);
            acc[p] = ffma2(ke, pv, acc[p]);
        }
        if (mm < 6) {                          // odd taps 169..179
            ull ko = k2[169 + 2*mm];
            #pragma unroll
            for (int p = 0; p < 8; p++) {
                const int i = 84 + mm + p;    // 84..96
                ull qv = (i <= 94) ? Q[i % 12] : ((i == 95) ? qx0 : qx1);
                acc[p] = ffma2(ko, qv, acc[p]);
            }
        }
    }

    // ---- store 16 outputs ----
    float* __restrict__ orow = out + (long long)row * t_out + t;
    float o[16];
    #pragma unroll
    for (int p = 0; p < 8; p++) upk2(acc[p], o[2*p], o[2*p+1]);

    if (t + OPT <= t_out && ((t_out & 3) == 0)) {
        #pragma unroll
        for (int q = 0; q < 4; q++)
            reinterpret_cast<float4*>(orow)[q] =
                make_float4(o[4*q], o[4*q+1], o[4*q+2], o[4*q+3]);
    } else {
        #pragma unroll
        for (int c = 0; c < OPT; c++)
            if (t + c < t_out) orow[c] = o[c];
    }
}

// Generic fallback for unexpected tap counts.
__global__ void fir_generic_kernel(const float* __restrict__ u,
                                   const float* __restrict__ kern,
                                   float* __restrict__ out,
                                   int t_out, int t_in, int kt)
{
    int t = blockIdx.x * blockDim.x + threadIdx.x;
    int row = blockIdx.y;
    if (t >= t_out) return;
    const float* urow = u + (long long)row * t_in;
    float acc = 0.0f;
    for (int i = 0; i < kt; i++)
        acc = fmaf(kern[kt - 1 - i], urow[t + i], acc);
    out[(long long)row * t_out + t] = acc;
}

extern "C" void kernel_launch(void* const* d_in, const int* in_sizes, int n_in,
                              void* d_out, int out_size)
{
    const float* u    = (const float*)d_in[0];
    const float* kern = (const float*)d_in[1];
    float* out        = (float*)d_out;

    const int kt      = in_sizes[1];
    const int b_total = (in_sizes[0] - out_size) / (kt - 1);
    const int t_out   = out_size / b_total;
    const int t_in    = in_sizes[0] / b_total;

    if (kt == KT) {
        dim3 grid((t_out + TILE_T - 1) / TILE_T, b_total);
        fir_f32x2_kernel<<<grid, NTHREADS>>>(u, kern, out, t_out, t_in);
    } else {
        dim3 grid((t_out + 255) / 256, b_total);
        fir_generic_kernel<<<grid, 256>>>(u, kern, out, t_out, t_in, kt);
    }
}

// round 4
// speedup vs baseline: 1.1439x; 1.1439x over previous
#include <cuda_runtime.h>

#define KT       181
#define OPT      16                   // outputs per thread
#define NTHREADS 256
#define TILE_T   (NTHREADS * OPT)     // 4096 outputs per block
#define SU_LEN   4288                 // >= TILE_T-OPT + 200, multiple of 16
#define KPAD     184                  // taps padded (multiple of 4)

// out[b,t] = sum_{i=0..KT-1} krev[i] * u[b,t+i],  krev[i] = kernel[KT-1-i]
// Register ring R[24] holds window floats f at slot f%24. Chunks of 8 taps,
// unrolled x3 so ring slots are compile-time constants (no shift MOVs).
__global__ __launch_bounds__(NTHREADS, 4)
void fir_scalar16_kernel(const float* __restrict__ u,
                         const float* __restrict__ kern,
                         float* __restrict__ out,
                         int t_out, int t_in)
{
    __shared__ __align__(16) float s_u[SU_LEN];
    __shared__ __align__(16) float s_k[KPAD];

    const int row = blockIdx.y;
    const int t0  = blockIdx.x * TILE_T;
    const int tid = threadIdx.x;

    const float* __restrict__ urow = u + (long long)row * t_in;

    // Stage reversed, zero-padded taps.
    for (int i = tid; i < KPAD; i += NTHREADS)
        s_k[i] = (i < KT) ? kern[KT - 1 - i] : 0.0f;

    // Stage input tile (vectorized when aligned).
    if (((t_in & 3) == 0) && ((t0 & 3) == 0)) {
        for (int i4 = tid; i4 < SU_LEN / 4; i4 += NTHREADS) {
            int g = t0 + i4 * 4;
            float4 v;
            if (g + 3 < t_in) {
                v = reinterpret_cast<const float4*>(urow + g)[0];
            } else {
                v.x = (g     < t_in) ? urow[g]     : 0.0f;
                v.y = (g + 1 < t_in) ? urow[g + 1] : 0.0f;
                v.z = (g + 2 < t_in) ? urow[g + 2] : 0.0f;
                v.w = (g + 3 < t_in) ? urow[g + 3] : 0.0f;
            }
            reinterpret_cast<float4*>(s_u)[i4] = v;
        }
    } else {
        for (int i = tid; i < SU_LEN; i += NTHREADS) {
            int g = t0 + i;
            s_u[i] = (g < t_in) ? urow[g] : 0.0f;
        }
    }
    __syncthreads();

    const int t_local = tid * OPT;          // multiple of 16 -> 64B aligned
    const int t       = t0 + t_local;
    if (t >= t_out) return;                 // no barriers below

    const float* __restrict__ w = s_u + t_local;

    float acc[OPT];
    #pragma unroll
    for (int c = 0; c < OPT; c++) acc[c] = 0.0f;

    // Init ring with floats 0..23.
    float R[24];
    #pragma unroll
    for (int q = 0; q < 6; q++) {
        float4 v = reinterpret_cast<const float4*>(w)[q];
        R[4*q+0] = v.x; R[4*q+1] = v.y; R[4*q+2] = v.z; R[4*q+3] = v.w;
    }

    // Main: 21 chunks of 8 taps (taps 0..167), 7 x (3 unrolled phases).
    #pragma unroll 1
    for (int oc = 0; oc < 7; oc++) {
        #pragma unroll
        for (int p = 0; p < 3; p++) {
            const int i  = oc * 24 + 8 * p;   // runtime tap base
            const int ib = 8 * p;             // static ring base (i % 24)

            // 8 taps via two broadcast LDS.128.
            float4 k0 = reinterpret_cast<const float4*>(s_k + i)[0];
            float4 k1 = reinterpret_cast<const float4*>(s_k + i)[1];
            const float kj[8] = {k0.x, k0.y, k0.z, k0.w, k1.x, k1.y, k1.z, k1.w};

            #pragma unroll
            for (int j = 0; j < 8; j++) {
                #pragma unroll
                for (int c = 0; c < OPT; c++)
                    acc[c] = fmaf(kj[j], R[(ib + j + c) % 24], acc[c]);
            }

            // Advance window: floats i+24 .. i+31 -> slots (ib+0..7)%24.
            float4 A = reinterpret_cast<const float4*>(w + i + 24)[0];
            float4 B = reinterpret_cast<const float4*>(w + i + 24)[1];
            R[(ib + 0) % 24] = A.x; R[(ib + 1) % 24] = A.y;
            R[(ib + 2) % 24] = A.z; R[(ib + 3) % 24] = A.w;
            R[(ib + 4) % 24] = B.x; R[(ib + 5) % 24] = B.y;
            R[(ib + 6) % 24] = B.z; R[(ib + 7) % 24] = B.w;
        }
    }

    // Chunk 21: taps 168..175, ring base 0 (168 % 24 == 0).
    {
        float4 k0 = reinterpret_cast<const float4*>(s_k + 168)[0];
        float4 k1 = reinterpret_cast<const float4*>(s_k + 168)[1];
        const float kj[8] = {k0.x, k0.y, k0.z, k0.w, k1.x, k1.y, k1.z, k1.w};
        #pragma unroll
        for (int j = 0; j < 8; j++) {
            #pragma unroll
            for (int c = 0; c < OPT; c++)
                acc[c] = fmaf(kj[j], R[(j + c) % 24], acc[c]);
        }
        // Advance: floats 192..199 -> slots 0..7.
        float4 A = reinterpret_cast<const float4*>(w + 192)[0];
        float4 B = reinterpret_cast<const float4*>(w + 192)[1];
        R[0] = A.x; R[1] = A.y; R[2] = A.z; R[3] = A.w;
        R[4] = B.x; R[5] = B.y; R[6] = B.z; R[7] = B.w;
    }

    // Tail: taps 176..180. Float f = 176+j+c at slot (8+j+c)%24.
    #pragma unroll
    for (int j = 0; j < 5; j++) {
        const float kj = s_k[176 + j];
        #pragma unroll
        for (int c = 0; c < OPT; c++)
            acc[c] = fmaf(kj, R[(8 + j + c) % 24], acc[c]);
    }

    // Store 16 outputs.
    float* __restrict__ orow = out + (long long)row * t_out + t;
    if (t + OPT <= t_out && ((t_out & 3) == 0)) {
        #pragma unroll
        for (int q = 0; q < 4; q++)
            reinterpret_cast<float4*>(orow)[q] =
                make_float4(acc[4*q], acc[4*q+1], acc[4*q+2], acc[4*q+3]);
    } else {
        #pragma unroll
        for (int c = 0; c < OPT; c++)
            if (t + c < t_out) orow[c] = acc[c];
    }
}

// Generic fallback for unexpected tap counts.
__global__ void fir_generic_kernel(const float* __restrict__ u,
                                   const float* __restrict__ kern,
                                   float* __restrict__ out,
                                   int t_out, int t_in, int kt)
{
    int t = blockIdx.x * blockDim.x + threadIdx.x;
    int row = blockIdx.y;
    if (t >= t_out) return;
    const float* urow = u + (long long)row * t_in;
    float acc = 0.0f;
    for (int i = 0; i < kt; i++)
        acc = fmaf(kern[kt - 1 - i], urow[t + i], acc);
    out[(long long)row * t_out + t] = acc;
}

extern "C" void kernel_launch(void* const* d_in, const int* in_sizes, int n_in,
                              void* d_out, int out_size)
{
    const float* u    = (const float*)d_in[0];
    const float* kern = (const float*)d_in[1];
    float* out        = (float*)d_out;

    const int kt      = in_sizes[1];
    const int b_total = (in_sizes[0] - out_size) / (kt - 1);
    const int t_out   = out_size / b_total;
    const int t_in    = in_sizes[0] / b_total;

    if (kt == KT) {
        dim3 grid((t_out + TILE_T - 1) / TILE_T, b_total);
        fir_scalar16_kernel<<<grid, NTHREADS>>>(u, kern, out, t_out, t_in);
    } else {
        dim3 grid((t_out + 255) / 256, b_total);
        fir_generic_kernel<<<grid, 256>>>(u, kern, out, t_out, t_in, kt);
    }
}

// round 5
// speedup vs baseline: 1.2082x; 1.0562x over previous
#include <cuda_runtime.h>

#define KT       181
#define OPT      16                   // outputs per thread
#define NTHREADS 256
#define TILE_T   (NTHREADS * OPT)     // 4096 outputs per block
#define SU_LEN   4288                 // >= TILE_T-OPT + 200, multiple of 16
#define KPAD     184                  // taps padded (multiple of 4)

// ---- SW128 swizzle on byte offsets: permutes 16B chunks within 128B rows ----
__device__ __forceinline__ unsigned swz(unsigned B) {
    return B ^ ((B >> 3) & 0x70u);
}
__device__ __forceinline__ float4 lds128_sw(const float* s, int foff) {
    unsigned B = swz((unsigned)foff * 4u);
    return *reinterpret_cast<const float4*>(reinterpret_cast<const char*>(s) + B);
}
__device__ __forceinline__ void sts128_sw(float* s, int foff, float4 v) {
    unsigned B = swz((unsigned)foff * 4u);
    *reinterpret_cast<float4*>(reinterpret_cast<char*>(s) + B) = v;
}
__device__ __forceinline__ void sts32_sw(float* s, int foff, float v) {
    unsigned B = swz((unsigned)foff * 4u);
    *reinterpret_cast<float*>(reinterpret_cast<char*>(s) + B) = v;
}

// out[b,t] = sum_{i=0..KT-1} krev[i] * u[b,t+i],  krev[i] = kernel[KT-1-i]
// Register ring R[24]; s_u stored XOR-swizzled so the 64B-lane-stride window
// LDS.128 is bank-conflict-free.
__global__ __launch_bounds__(NTHREADS, 4)
void fir_swz16_kernel(const float* __restrict__ u,
                      const float* __restrict__ kern,
                      float* __restrict__ out,
                      int t_out, int t_in)
{
    __shared__ __align__(128) float s_u[SU_LEN];
    __shared__ __align__(16)  float s_k[KPAD];

    const int row = blockIdx.y;
    const int t0  = blockIdx.x * TILE_T;
    const int tid = threadIdx.x;

    const float* __restrict__ urow = u + (long long)row * t_in;

    // Stage reversed, zero-padded taps (not swizzled; broadcast reads).
    for (int i = tid; i < KPAD; i += NTHREADS)
        s_k[i] = (i < KT) ? kern[KT - 1 - i] : 0.0f;

    // Stage input tile into swizzled shared.
    if (((t_in & 3) == 0) && ((t0 & 3) == 0)) {
        for (int i4 = tid; i4 < SU_LEN / 4; i4 += NTHREADS) {
            int g = t0 + i4 * 4;
            float4 v;
            if (g + 3 < t_in) {
                v = reinterpret_cast<const float4*>(urow + g)[0];
            } else {
                v.x = (g     < t_in) ? urow[g]     : 0.0f;
                v.y = (g + 1 < t_in) ? urow[g + 1] : 0.0f;
                v.z = (g + 2 < t_in) ? urow[g + 2] : 0.0f;
                v.w = (g + 3 < t_in) ? urow[g + 3] : 0.0f;
            }
            sts128_sw(s_u, i4 * 4, v);
        }
    } else {
        for (int i = tid; i < SU_LEN; i += NTHREADS) {
            int g = t0 + i;
            sts32_sw(s_u, i, (g < t_in) ? urow[g] : 0.0f);
        }
    }
    __syncthreads();

    const int t_local = tid * OPT;          // multiple of 16
    const int t       = t0 + t_local;
    if (t >= t_out) return;                 // no barriers below

    float acc[OPT];
    #pragma unroll
    for (int c = 0; c < OPT; c++) acc[c] = 0.0f;

    // Init ring with window floats 0..23.
    float R[24];
    #pragma unroll
    for (int q = 0; q < 6; q++) {
        float4 v = lds128_sw(s_u, t_local + 4 * q);
        R[4*q+0] = v.x; R[4*q+1] = v.y; R[4*q+2] = v.z; R[4*q+3] = v.w;
    }

    // Main: 21 chunks of 8 taps (taps 0..167), 7 x (3 unrolled phases).
    #pragma unroll 1
    for (int oc = 0; oc < 7; oc++) {
        #pragma unroll
        for (int p = 0; p < 3; p++) {
            const int i  = oc * 24 + 8 * p;   // runtime tap base
            const int ib = 8 * p;             // static ring base (i % 24)

            // 8 taps via two broadcast LDS.128.
            float4 k0 = reinterpret_cast<const float4*>(s_k + i)[0];
            float4 k1 = reinterpret_cast<const float4*>(s_k + i)[1];
            const float kj[8] = {k0.x, k0.y, k0.z, k0.w, k1.x, k1.y, k1.z, k1.w};

            #pragma unroll
            for (int j = 0; j < 8; j++) {
                #pragma unroll
                for (int c = 0; c < OPT; c++)
                    acc[c] = fmaf(kj[j], R[(ib + j + c) % 24], acc[c]);
            }

            // Advance window: floats i+24 .. i+31 -> slots (ib+0..7)%24.
            float4 A = lds128_sw(s_u, t_local + i + 24);
            float4 B = lds128_sw(s_u, t_local + i + 28);
            R[(ib + 0) % 24] = A.x; R[(ib + 1) % 24] = A.y;
            R[(ib + 2) % 24] = A.z; R[(ib + 3) % 24] = A.w;
            R[(ib + 4) % 24] = B.x; R[(ib + 5) % 24] = B.y;
            R[(ib + 6) % 24] = B.z; R[(ib + 7) % 24] = B.w;
        }
    }

    // Chunk 21: taps 168..175, ring base 0 (168 % 24 == 0).
    {
        float4 k0 = reinterpret_cast<const float4*>(s_k + 168)[0];
        float4 k1 = reinterpret_cast<const float4*>(s_k + 168)[1];
        const float kj[8] = {k0.x, k0.y, k0.z, k0.w, k1.x, k1.y, k1.z, k1.w};
        #pragma unroll
        for (int j = 0; j < 8; j++) {
            #pragma unroll
            for (int c = 0; c < OPT; c++)
                acc[c] = fmaf(kj[j], R[(j + c) % 24], acc[c]);
        }
        float4 A = lds128_sw(s_u, t_local + 192);
        float4 B = lds128_sw(s_u, t_local + 196);
        R[0] = A.x; R[1] = A.y; R[2] = A.z; R[3] = A.w;
        R[4] = B.x; R[5] = B.y; R[6] = B.z; R[7] = B.w;
    }

    // Tail: taps 176..180. Float f = 176+j+c at slot (8+j+c)%24.
    #pragma unroll
    for (int j = 0; j < 5; j++) {
        const float kj = s_k[176 + j];
        #pragma unroll
        for (int c = 0; c < OPT; c++)
            acc[c] = fmaf(kj, R[(8 + j + c) % 24], acc[c]);
    }

    // Store 16 outputs.
    float* __restrict__ orow = out + (long long)row * t_out + t;
    if (t + OPT <= t_out && ((t_out & 3) == 0)) {
        #pragma unroll
        for (int q = 0; q < 4; q++)
            reinterpret_cast<float4*>(orow)[q] =
                make_float4(acc[4*q], acc[4*q+1], acc[4*q+2], acc[4*q+3]);
    } else {
        #pragma unroll
        for (int c = 0; c < OPT; c++)
            if (t + c < t_out) orow[c] = acc[c];
    }
}

// Generic fallback for unexpected tap counts.
__global__ void fir_generic_kernel(const float* __restrict__ u,
                                   const float* __restrict__ kern,
                                   float* __restrict__ out,
                                   int t_out, int t_in, int kt)
{
    int t = blockIdx.x * blockDim.x + threadIdx.x;
    int row = blockIdx.y;
    if (t >= t_out) return;
    const float* urow = u + (long long)row * t_in;
    float acc = 0.0f;
    for (int i = 0; i < kt; i++)
        acc = fmaf(kern[kt - 1 - i], urow[t + i], acc);
    out[(long long)row * t_out + t] = acc;
}

extern "C" void kernel_launch(void* const* d_in, const int* in_sizes, int n_in,
                              void* d_out, int out_size)
{
    const float* u    = (const float*)d_in[0];
    const float* kern = (const float*)d_in[1];
    float* out        = (float*)d_out;

    const int kt      = in_sizes[1];
    const int b_total = (in_sizes[0] - out_size) / (kt - 1);
    const int t_out   = out_size / b_total;
    const int t_in    = in_sizes[0] / b_total;

    if (kt == KT) {
        dim3 grid((t_out + TILE_T - 1) / TILE_T, b_total);
        fir_swz16_kernel<<<grid, NTHREADS>>>(u, kern, out, t_out, t_in);
    } else {
        dim3 grid((t_out + 255) / 256, b_total);
        fir_generic_kernel<<<grid, 256>>>(u, kern, out, t_out, t_in, kt);
    }
}